// round 5
// baseline (speedup 1.0000x reference)
#include <cuda_runtime.h>

#define CIN   64
#define CO    64
#define FEAT  1152
#define N1    576
#define N2    4096
#define HW    128
#define TILE  32
#define NTH   512
#define FSP   36
#define PER_TENSOR (4 * CO * HW * HW)

#define SMEM_FLOATS (FEAT * FSP + 3 * TILE * 64)
#define SMEM_BYTES  (SMEM_FLOATS * 4)    // 190,464 B

typedef unsigned long long ull;

// packed duplicated weights:
// W1pd[f][ch=0..4][c=0..63][4]   taps {2ch,2ch+1} each duplicated  (5.9 MB)
// W2pd[cg][f][ch=0..1][colB][4]  cols {cg*512+(2ch+i/2)*128+colB} dup (37.7 MB)
__device__ float W1pd[FEAT * 5 * 64 * 4];
__device__ float W2pd[8LL * FEAT * 2 * 128 * 4];

__global__ void pack_w1(const float* __restrict__ W1) {
    int idx = blockIdx.x * blockDim.x + threadIdx.x;
    if (idx >= FEAT * 5 * 64 * 4) return;
    int i  = idx & 3;
    int c  = (idx >> 2) & 63;
    int ch = (idx >> 8) % 5;
    int f  = idx / 1280;
    int tap = ch * 2 + (i >> 1);
    W1pd[idx] = (tap < 9) ? W1[(size_t)f * N1 + c * 9 + tap] : 0.0f;
}

__global__ void pack_w2(const float* __restrict__ W2) {
    long long idx = (long long)blockIdx.x * blockDim.x + threadIdx.x;
    if (idx >= 8LL * FEAT * 2 * 128 * 4) return;
    int i    = (int)(idx & 3);
    int colB = (int)((idx >> 2) & 127);
    int ch   = (int)((idx >> 9) & 1);
    int f    = (int)((idx >> 10) % FEAT);
    int cg   = (int)(idx / (1024LL * FEAT));
    int col  = cg * 512 + (ch * 2 + (i >> 1)) * 128 + colB;
    W2pd[idx] = W2[(size_t)f * N2 + col];
}

__device__ __forceinline__ void fma2(ull& a, ull x, ull y) {
    asm("fma.rn.f32x2 %0, %1, %2, %0;" : "+l"(a) : "l"(x), "l"(y));
}
__device__ __forceinline__ float2 unpk(ull v) {
    float2 f; asm("mov.b64 {%0, %1}, %2;" : "=f"(f.x), "=f"(f.y) : "l"(v)); return f;
}

__global__ __launch_bounds__(NTH, 1)
void fused_kpn_kernel(const float* __restrict__ x,
                      const float* __restrict__ m,
                      const float* __restrict__ s,
                      const float* __restrict__ b1,
                      const float* __restrict__ b2,
                      float* __restrict__ out)
{
    extern __shared__ float smf[];
    float* featT = smf;                       // [FEAT][FSP]
    float* yr_s  = smf + FEAT * FSP;          // [32][64]
    float* mr_s  = yr_s + TILE * 64;
    float* sr_s  = mr_s + TILE * 64;

    const int tid  = threadIdx.x;
    const int pix0 = blockIdx.x * TILE;
    const int b    = pix0 >> 14;
    const int h    = (pix0 >> 7) & 127;
    const int w0   = pix0 & 127;

    // ---- gather feat tile (transposed): featT[f][pix] ----
    const float* base_x = x + (size_t)b * (CIN * HW * HW);
    const float* base_m = m + (size_t)b * (CIN * HW * HW);
    for (int idx = tid; idx < TILE * FEAT; idx += NTH) {
        int pix = idx & 31;
        int f   = idx >> 5;
        const float* src = base_x;
        int fr = f;
        if (f >= N1) { src = base_m; fr = f - N1; }
        int c  = fr / 9;
        int k  = fr - c * 9;
        int kh = k / 3;
        int kw = k - kh * 3;
        int hh = max(0, min(HW - 1, h + kh - 1));
        int ww = max(0, min(HW - 1, w0 + pix + kw - 1));
        featT[f * FSP + pix] = src[(c * HW + hh) * HW + ww];
    }
    __syncthreads();

    const ull* featT2 = (const ull*)featT;    // [f][18] pixel pairs

    // ============ Phase A: thread owns channel cA (9 taps), 4 pixels ========
    {
        const int cA  = tid & 63;
        const int pgA = tid >> 6;
        ull acc[9][2];
        #pragma unroll
        for (int k = 0; k < 9; k++) { acc[k][0] = 0ull; acc[k][1] = 0ull; }

        const ulonglong2* wq = (const ulonglong2*)W1pd + cA;
        #pragma unroll 2
        for (int f = 0; f < FEAT; f++) {
            const ulonglong2* w = wq + (size_t)f * 320;   // 5*64 per f
            ulonglong2 q0 = w[0];
            ulonglong2 q1 = w[64];
            ulonglong2 q2 = w[128];
            ulonglong2 q3 = w[192];
            ulonglong2 q4 = w[256];
            ulonglong2 vv = *(const ulonglong2*)(featT2 + f * 18 + pgA * 2);
            fma2(acc[0][0], vv.x, q0.x); fma2(acc[0][1], vv.y, q0.x);
            fma2(acc[1][0], vv.x, q0.y); fma2(acc[1][1], vv.y, q0.y);
            fma2(acc[2][0], vv.x, q1.x); fma2(acc[2][1], vv.y, q1.x);
            fma2(acc[3][0], vv.x, q1.y); fma2(acc[3][1], vv.y, q1.y);
            fma2(acc[4][0], vv.x, q2.x); fma2(acc[4][1], vv.y, q2.x);
            fma2(acc[5][0], vv.x, q2.y); fma2(acc[5][1], vv.y, q2.y);
            fma2(acc[6][0], vv.x, q3.x); fma2(acc[6][1], vv.y, q3.x);
            fma2(acc[7][0], vv.x, q3.y); fma2(acc[7][1], vv.y, q3.y);
            fma2(acc[8][0], vv.x, q4.x); fma2(acc[8][1], vv.y, q4.x);
        }

        float yrv[4] = {0,0,0,0}, mrv[4] = {0,0,0,0}, srv[4] = {0,0,0,0};
        #pragma unroll
        for (int k = 0; k < 9; k++) {
            const int j  = cA * 9 + k;
            const float bj = b1[j];
            const int kh = k / 3;
            const int kw = k - kh * 3;
            const int hh = max(0, min(HW - 1, h + kh - 1));
            const float* sp_row = s + (((size_t)b * CIN + cA) * HW + hh) * HW;
            float2 a01 = unpk(acc[k][0]);
            float2 a23 = unpk(acc[k][1]);
            float av[4] = { a01.x, a01.y, a23.x, a23.y };
            #pragma unroll
            for (int p = 0; p < 4; p++) {
                int pix = pgA * 4 + p;
                float v  = av[p] + bj;
                float aw = fabsf(v);
                int ww = max(0, min(HW - 1, w0 + pix + kw - 1));
                yrv[p] += featT[j * FSP + pix] * v;
                mrv[p] += featT[(N1 + j) * FSP + pix] * aw;
                srv[p] += sp_row[ww] * aw;
            }
        }
        #pragma unroll
        for (int p = 0; p < 4; p++) {
            int pix = pgA * 4 + p;
            yr_s[pix * 64 + cA] = yrv[p];
            mr_s[pix * 64 + cA] = mrv[p];
            sr_s[pix * 64 + cA] = srv[p];
        }
    }
    __syncthreads();

    // ============ Phase B: w2 = feat @ W2 + b2, fused channel sum ===========
    const int colB = tid & 127;
    const int pgB  = tid >> 7;
    float ya[8], ma[8], sa[8];
    #pragma unroll
    for (int p = 0; p < 8; p++) { ya[p] = 0.0f; ma[p] = 0.0f; sa[p] = 0.0f; }

    const ulonglong2* w2q = (const ulonglong2*)W2pd;
    for (int cg = 0; cg < 8; cg++) {
        ull acc[4][4];
        #pragma unroll
        for (int i = 0; i < 4; i++)
            #pragma unroll
            for (int pp = 0; pp < 4; pp++) acc[i][pp] = 0ull;

        const ulonglong2* wbase = w2q + ((size_t)cg * FEAT) * 256 + colB;
        #pragma unroll 4
        for (int f = 0; f < FEAT; f++) {
            const ulonglong2* w = wbase + (size_t)f * 256;
            ulonglong2 t0 = w[0];      // cols colB, colB+128 (dup pairs)
            ulonglong2 t1 = w[128];    // cols colB+256, colB+384
            const ulonglong2* fp = (const ulonglong2*)(featT2 + f * 18 + pgB * 4);
            ulonglong2 va = fp[0];
            ulonglong2 vb = fp[1];
            fma2(acc[0][0], va.x, t0.x); fma2(acc[0][1], va.y, t0.x);
            fma2(acc[0][2], vb.x, t0.x); fma2(acc[0][3], vb.y, t0.x);
            fma2(acc[1][0], va.x, t0.y); fma2(acc[1][1], va.y, t0.y);
            fma2(acc[1][2], vb.x, t0.y); fma2(acc[1][3], vb.y, t0.y);
            fma2(acc[2][0], va.x, t1.x); fma2(acc[2][1], va.y, t1.x);
            fma2(acc[2][2], vb.x, t1.x); fma2(acc[2][3], vb.y, t1.x);
            fma2(acc[3][0], va.x, t1.y); fma2(acc[3][1], va.y, t1.y);
            fma2(acc[3][2], vb.x, t1.y); fma2(acc[3][3], vb.y, t1.y);
        }

        #pragma unroll
        for (int i = 0; i < 4; i++) {
            const int j = cg * 512 + colB + i * 128;
            const int c = j >> 6;
            const float bb = b2[j];
            #pragma unroll
            for (int pp = 0; pp < 4; pp++) {
                float2 a = unpk(acc[i][pp]);
                int pixA = pgB * 8 + 2 * pp;
                float yrA = yr_s[pixA * 64 + c], yrB = yr_s[(pixA + 1) * 64 + c];
                float mrA = mr_s[pixA * 64 + c], mrB = mr_s[(pixA + 1) * 64 + c];
                float srA = sr_s[pixA * 64 + c], srB = sr_s[(pixA + 1) * 64 + c];
                float vA = a.x + bb, vB = a.y + bb;
                float aA = fabsf(vA), aB = fabsf(vB);
                ya[2 * pp]     += yrA * vA;  ya[2 * pp + 1] += yrB * vB;
                ma[2 * pp]     += mrA * aA;  ma[2 * pp + 1] += mrB * aB;
                sa[2 * pp]     += srA * aA;  sa[2 * pp + 1] += srB * aB;
            }
        }
    }
    __syncthreads();

    // ============ stage per-half partials, combine, write ===================
    {
        const int half = colB >> 6;
        const int o    = colB & 63;
        float* sty = smf + half * 3 * 2080;   // [32][65] each
        float* stm = sty + 2080;
        float* sts = stm + 2080;
        #pragma unroll
        for (int p = 0; p < 8; p++) {
            int pix = pgB * 8 + p;
            sty[pix * 65 + o] = ya[p];
            stm[pix * 65 + o] = ma[p];
            sts[pix * 65 + o] = sa[p];
        }
    }
    __syncthreads();

    for (int t = tid; t < TILE * CO; t += NTH) {
        int o   = t >> 5;
        int pix = t & 31;
        float y  = smf[pix * 65 + o]             + smf[3 * 2080 + pix * 65 + o];
        float mm = (smf[2080 + pix * 65 + o]     + smf[4 * 2080 + pix * 65 + o]) /
                   (smf[2 * 2080 + pix * 65 + o] + smf[5 * 2080 + pix * 65 + o]);
        size_t gi = (((size_t)b * CO + o) * HW + h) * HW + w0 + pix;
        out[gi]                  = y;
        out[gi + PER_TENSOR]     = mm;
        out[gi + 2 * PER_TENSOR] = 1.0f;
    }
}

extern "C" void kernel_launch(void* const* d_in, const int* in_sizes, int n_in,
                              void* d_out, int out_size)
{
    const float* x  = (const float*)d_in[0];
    const float* m  = (const float*)d_in[1];
    const float* s  = (const float*)d_in[2];
    const float* W1 = (const float*)d_in[3];
    const float* b1 = (const float*)d_in[4];
    const float* W2 = (const float*)d_in[5];
    const float* b2 = (const float*)d_in[6];
    float* out = (float*)d_out;

    cudaFuncSetAttribute(fused_kpn_kernel,
                         cudaFuncAttributeMaxDynamicSharedMemorySize, SMEM_BYTES);

    {
        int n1 = FEAT * 5 * 64 * 4;
        pack_w1<<<(n1 + 255) / 256, 256>>>(W1);
        long long n2 = 8LL * FEAT * 2 * 128 * 4;
        pack_w2<<<(int)((n2 + 255) / 256), 256>>>(W2);
    }

    const int nblocks = (4 * HW * HW) / TILE;   // 2048
    fused_kpn_kernel<<<nblocks, NTH, SMEM_BYTES>>>(x, m, s, b1, b2, out);
}